// round 5
// baseline (speedup 1.0000x reference)
#include <cuda_runtime.h>
#include <cuda_bf16.h>

// Problem constants (fixed by the reference)
#define CSEG 4096
#define ED   16
#define PIX  (1024*1024)
#define NEDGE 16384
#define DELTA_VAR  0.5f
#define DELTA_DIST 1.5f

// Scratch (device globals — no allocation allowed)
__device__ __align__(128) float g_sums[CSEG * ED];   // 256 KB segment sums
__device__ __align__(128) float g_means[CSEG * ED];  // 256 KB segment means
__device__ float g_counts[CSEG];
__device__ float g_invn[CSEG];
__device__ float g_acc[2];   // [0]=inter sum, [1]=intra sum

// ---------------------------------------------------------------------------
// Vector reduction to global memory (sm_90+): one L2 atomic op for 4 floats.
__device__ __forceinline__ void red_add_v4(float* addr, float a, float b, float c, float d) {
    asm volatile("red.global.add.v4.f32 [%0], {%1, %2, %3, %4};"
                 :: "l"(addr), "f"(a), "f"(b), "f"(c), "f"(d) : "memory");
}

__device__ __forceinline__ float warp_reduce(float v) {
    v += __shfl_down_sync(0xFFFFFFFFu, v, 16);
    v += __shfl_down_sync(0xFFFFFFFFu, v, 8);
    v += __shfl_down_sync(0xFFFFFFFFu, v, 4);
    v += __shfl_down_sync(0xFFFFFFFFu, v, 2);
    v += __shfl_down_sync(0xFFFFFFFFu, v, 1);
    return v;
}

// Block reduction: returns full sum on thread 0.
__device__ __forceinline__ float block_reduce(float v) {
    __shared__ float s[32];
    int lane = threadIdx.x & 31;
    int wid  = threadIdx.x >> 5;
    v = warp_reduce(v);
    if (lane == 0) s[wid] = v;
    __syncthreads();
    int nw = (blockDim.x + 31) >> 5;
    v = (threadIdx.x < nw) ? s[threadIdx.x] : 0.0f;
    if (wid == 0) v = warp_reduce(v);
    return v;
}

// ---------------------------------------------------------------------------
// k0: zero the scratch accumulators (graph replays re-run this every launch)
__global__ void k_zero() {
    int i = blockIdx.x * blockDim.x + threadIdx.x;
    if (i < CSEG * ED) g_sums[i] = 0.0f;
    if (i < CSEG)      g_counts[i] = 0.0f;
    if (i < 2)         g_acc[i] = 0.0f;
}

// k1: segment sums + counts. One thread per pixel; 16 coalesced strided loads
// (stride = PIX floats per channel plane), then 4 vector reds + 1 scalar red.
__global__ void __launch_bounds__(256) k_segsum(const float* __restrict__ emb,
                                                const int*   __restrict__ seg) {
    int p = blockIdx.x * blockDim.x + threadIdx.x;
    int c = seg[p];
    float v[ED];
#pragma unroll
    for (int e = 0; e < ED; e++) v[e] = emb[(size_t)e * PIX + p];
    float* base = &g_sums[c * ED];
    red_add_v4(base +  0, v[0],  v[1],  v[2],  v[3]);
    red_add_v4(base +  4, v[4],  v[5],  v[6],  v[7]);
    red_add_v4(base +  8, v[8],  v[9],  v[10], v[11]);
    red_add_v4(base + 12, v[12], v[13], v[14], v[15]);
    atomicAdd(&g_counts[c], 1.0f);
}

// k2: means = sums / max(counts, 1); also 1/n per segment.
__global__ void k_means() {
    int i = blockIdx.x * blockDim.x + threadIdx.x;   // over CSEG*ED
    int c = i >> 4;
    float n = fmaxf(g_counts[c], 1.0f);
    g_means[i] = g_sums[i] / n;
    if ((i & 15) == 0) g_invn[c] = 1.0f / n;
}

// k3: inter-superpixel term over RAG edges.
__global__ void __launch_bounds__(256) k_inter(const int*   __restrict__ edges,
                                               const float* __restrict__ w) {
    int i = blockIdx.x * blockDim.x + threadIdx.x;   // over NEDGE
    int u = edges[i];
    int v = edges[NEDGE + i];
    const float4* mu = (const float4*)&g_means[u * ED];
    const float4* mv = (const float4*)&g_means[v * ED];
    float dot = 0.0f;
#pragma unroll
    for (int j = 0; j < 4; j++) {
        float4 a = mu[j], b = mv[j];
        dot += a.x * b.x + a.y * b.y + a.z * b.z + a.w * b.w;
    }
    float d_inter = 1.0f - dot;
    float t = fmaxf(DELTA_DIST - d_inter * w[i], 0.0f);
    t = block_reduce(t);
    if (threadIdx.x == 0) atomicAdd(&g_acc[0], t);
}

// k4: intra-superpixel term. Re-reads embeddings (L2-resident from k1),
// gathers the 64B mean row per pixel, hinge, per-block reduce, 1 atomic/block.
__global__ void __launch_bounds__(256) k_intra(const float* __restrict__ emb,
                                               const int*   __restrict__ seg) {
    int p = blockIdx.x * blockDim.x + threadIdx.x;
    int c = seg[p];
    const float4* m = (const float4*)&g_means[c * ED];
    float4 m0 = m[0], m1 = m[1], m2 = m[2], m3 = m[3];
    float v[ED];
#pragma unroll
    for (int e = 0; e < ED; e++) v[e] = emb[(size_t)e * PIX + p];
    float dot = m0.x * v[0]  + m0.y * v[1]  + m0.z * v[2]  + m0.w * v[3]
              + m1.x * v[4]  + m1.y * v[5]  + m1.z * v[6]  + m1.w * v[7]
              + m2.x * v[8]  + m2.y * v[9]  + m2.z * v[10] + m2.w * v[11]
              + m3.x * v[12] + m3.y * v[13] + m3.z * v[14] + m3.w * v[15];
    // d_intra - delta_var = (1 - dot) - 0.5 = 0.5 - dot
    float t = fmaxf(0.5f - dot, 0.0f) * g_invn[c];
    t = block_reduce(t);
    if (threadIdx.x == 0) atomicAdd(&g_acc[1], t);
}

// k5: finalize scalar: ALPHA * inter/NE + BETA * intra/C
__global__ void k_final(float* __restrict__ out) {
    out[0] = g_acc[0] / (float)NEDGE + g_acc[1] / (float)CSEG;
}

// ---------------------------------------------------------------------------
extern "C" void kernel_launch(void* const* d_in, const int* in_sizes, int n_in,
                              void* d_out, int out_size) {
    const float* emb   = (const float*)d_in[0];   // (1,16,1024,1024) f32
    const float* w     = (const float*)d_in[1];   // (NE,) f32
    const int*   seg   = (const int*)  d_in[2];   // (1,1,1024,1024) i32
    const int*   edges = (const int*)  d_in[3];   // (2,NE) i32
    float*       out   = (float*)d_out;

    k_zero  <<<(CSEG * ED + 255) / 256, 256>>>();
    k_segsum<<<PIX / 256, 256>>>(emb, seg);
    k_means <<<(CSEG * ED) / 256, 256>>>();
    k_inter <<<NEDGE / 256, 256>>>(edges, w);
    k_intra <<<PIX / 256, 256>>>(emb, seg);
    k_final <<<1, 1>>>(out);
}